// round 13
// baseline (speedup 1.0000x reference)
#include <cuda_runtime.h>
#include <cstdint>

// SAME-padded stride-1 3x3 conv, NHWC fp32, tf32 mma.sync implicit GEMM.
// Round 13: 4-row CTAs (224px x 64couts, 4 warps of 112x32, 128 thr),
// 2 CTAs/SM for desynchronized latency hiding; B fragments LDG.128 from
// pre-packed w_frag with one-tap register prefetch (bx double buffer).

#define CB    32
#define CH    56
#define CW    56
#define CCIN  128
#define CCOUT 256
#define NPIX  (CB * CH * CW)      // 100352
#define KTOT  1152

#define BN 64
#define NTHREADS 128              // 4 warps, 2(M) x 2(N), warp 112x32

#define HR 6                      // halo rows  (4 + 2)
#define HC 58                     // halo cols  (56 + 2)
#define HPIX (HR * HC)            // 348
#define AROW 40                   // words per halo pixel (32 data + 8 pad)
#define A_STAGE_W (HPIX * AROW)   // 13920 words (55680 B)
#define SMEM_BYTES (2 * A_STAGE_W * 4)   // 111360 -> 2 CTAs/SM

#define XGROUPS (NPIX * CCIN / 8 / 256)  // 6272 blocks for x-prep
#define WFRAG_TOTAL (KTOT * CCOUT)       // 294912 floats

// ---------------- scratch ----------------
__device__ __align__(1024) float g_x_t[NPIX * CCIN];     // tf32(rne), cin-permuted
// w_frag: [B0=8][tap=9][chunk=4][u=4][jh=2][lane=32][q=4] floats
__device__ __align__(1024) float g_w_f[WFRAG_TOTAL];

// ---------------- helpers ----------------
__device__ __forceinline__ uint32_t smem_u32(const void* p) {
    uint32_t a;
    asm("{ .reg .u64 t; cvta.to.shared.u64 t, %1; cvt.u32.u64 %0, t; }"
        : "=r"(a) : "l"(p));
    return a;
}

__device__ __forceinline__ void cp16(uint32_t dst, const void* src, uint32_t srcsz) {
    asm volatile("cp.async.cg.shared.global [%0], [%1], 16, %2;"
                 :: "r"(dst), "l"(src), "r"(srcsz) : "memory");
}
#define CP_COMMIT() asm volatile("cp.async.commit_group;" ::: "memory")
#define CP_WAIT0()  asm volatile("cp.async.wait_group 0;" ::: "memory")

__device__ __forceinline__ void mma_tf32(float c[4], const uint32_t a[4],
                                         uint32_t b0, uint32_t b1) {
    asm volatile(
        "mma.sync.aligned.m16n8k8.row.col.f32.tf32.tf32.f32 "
        "{%0,%1,%2,%3}, {%4,%5,%6,%7}, {%8,%9}, {%0,%1,%2,%3};"
        : "+f"(c[0]), "+f"(c[1]), "+f"(c[2]), "+f"(c[3])
        : "r"(a[0]), "r"(a[1]), "r"(a[2]), "r"(a[3]),
          "r"(b0), "r"(b1));
}

__device__ __forceinline__ float rna_tf32(float v) {
    uint32_t r;
    asm("cvt.rna.tf32.f32 %0, %1;" : "=r"(r) : "f"(v));
    return __uint_as_float(r);
}

// ---------------- merged pre-kernel (unchanged from R12) ----------------
__global__ void k_prep(const float* __restrict__ x, const float* __restrict__ w,
                       float* __restrict__ gx, float* __restrict__ gwf)
{
    const int bid = blockIdx.x;
    if (bid < XGROUPS) {
        const int g = bid * 256 + threadIdx.x;
        const float4* i4 = (const float4*)(x) + g * 2;
        float4 a = i4[0];   // c0..c3
        float4 b = i4[1];   // c4..c7
        float4 o0, o1;
        o0.x = rna_tf32(a.x); o0.y = rna_tf32(b.x);
        o0.z = rna_tf32(a.y); o0.w = rna_tf32(b.y);
        o1.x = rna_tf32(a.z); o1.y = rna_tf32(b.z);
        o1.z = rna_tf32(a.w); o1.w = rna_tf32(b.w);
        float4* o4 = (float4*)(gx) + g * 2;
        o4[0] = o0;
        o4[1] = o1;
    } else {
        const int f = (bid - XGROUPS) * 256 + threadIdx.x;  // 0..294911
        const int q     = f & 3;
        const int lane  = (f >> 2) & 31;
        const int jh    = (f >> 7) & 1;
        const int u     = (f >> 8) & 3;
        const int chunk = (f >> 10) & 3;
        const int rem   = f >> 12;          // B0*9 + tap
        const int B0    = rem / 9;
        const int tap   = rem - B0 * 9;
        const int lr = lane >> 2, lc = lane & 3;
        const int j = jh * 2 + (q >> 1);
        const int e = q & 1;
        const int cin  = (chunk * 4 + j) * 8 + lc + e * 4;
        const int cout = B0 * 32 + u * 8 + lr;
        gwf[f] = rna_tf32(w[(size_t)(tap * 128 + cin) * CCOUT + cout]);
    }
}

// ---------------- main kernel ----------------
__global__ __launch_bounds__(NTHREADS, 2)
void conv_mma(const float* __restrict__ xt, const float* __restrict__ wf,
              const float* __restrict__ bias, float* __restrict__ out)
{
    extern __shared__ float smem[];
    const uint32_t sbase = smem_u32(smem);

    const int tid  = threadIdx.x;
    const int wid  = tid >> 5;
    const int lane = tid & 31;
    const int lr   = lane >> 2;    // 0..7
    const int lc   = lane & 3;     // 0..3
    const int bn = blockIdx.x;     // 0..3    (cout block of 64)
    const int n  = blockIdx.y / 14;          // image
    const int h0 = (blockIdx.y % 14) * 4;    // first output row

    const int warp_m = wid >> 1;   // 0..1
    const int warp_n = wid & 1;    // 0..1

    // ---- fragment A base offsets (words, incl. lc*2 k-offset) ----
    int abase[7][2];
    #pragma unroll
    for (int t = 0; t < 7; ++t)
        #pragma unroll
        for (int h = 0; h < 2; ++h) {
            const int m = warp_m * 112 + t * 16 + lr + h * 8;   // 0..223
            const int r = m / 56, c = m % 56;
            abase[t][h] = ((r + 1) * HC + (c + 1)) * AROW + lc * 2;
        }

    const float* xbase = xt + (size_t)(n * (CH * CW)) * CCIN;
    const float4* wf4 = (const float4*)(wf)
                      + (size_t)(bn * 2 + warp_n) * (36 * 256) + lane;

    float acc[7][4][4];
    #pragma unroll
    for (int t = 0; t < 7; ++t)
        #pragma unroll
        for (int u = 0; u < 4; ++u)
            #pragma unroll
            for (int r = 0; r < 4; ++r)
                acc[t][u][r] = 0.0f;

    // ---- fill 2 halo rows (rq = 0..2) of A buffer `buf` for `chunk` ----
    auto fill_A_rows = [&](int chunk, int buf, int rq) {
        const uint32_t dst0 = sbase + (uint32_t)buf * (A_STAGE_W * 4);
        for (int idx = tid; idx < 2 * HC * 8; idx += NTHREADS) {
            const int pix = idx >> 3;            // 0..115
            const int seg = idx & 7;
            const int hr = (pix >= HC) ? 1 : 0;
            const int wc = pix - hr * HC;
            const int h = h0 - 1 + rq * 2 + hr, w2 = wc - 1;
            const bool ok = ((unsigned)h < CH) && ((unsigned)w2 < CW);
            const float* src = xbase
                + (ok ? ((size_t)(h * CW + w2) * CCIN + chunk * 32 + seg * 4) : 0);
            cp16(dst0 + (uint32_t)(rq * 2 * HC + pix) * (AROW * 4) + seg * 16,
                 src, ok ? 16u : 0u);
        }
    };

    // ---- prologue: A(chunk0) + B prefetch (chunk0, tap0) ----
    #pragma unroll
    for (int rq = 0; rq < 3; ++rq) fill_A_rows(0, 0, rq);
    CP_COMMIT();

    float4 bx[2][8];
    #pragma unroll
    for (int ui = 0; ui < 8; ++ui)
        bx[0][ui] = wf4[ui * 32];      // (tap0, chunk0) block

    #pragma unroll 1
    for (int chunk = 0; chunk < 4; ++chunk) {
        CP_WAIT0();
        __syncthreads();

        const float* As = smem + (chunk & 1) * A_STAGE_W;

        #pragma unroll 1
        for (int tap = 0; tap < 9; ++tap) {
            const int par = (chunk + tap) & 1;     // phase parity (9 odd)

            // ---- prefetch next tap's B into the other buffer ----
            if (tap < 8) {
                const float4* wn = wf4 + ((tap + 1) * 4 + chunk) * 256;
                #pragma unroll
                for (int ui = 0; ui < 8; ++ui)
                    bx[par ^ 1][ui] = wn[ui * 32];
            } else if (chunk < 3) {
                const float4* wn = wf4 + (chunk + 1) * 256;   // (tap0, chunk+1)
                #pragma unroll
                for (int ui = 0; ui < 8; ++ui)
                    bx[par ^ 1][ui] = wn[ui * 32];
            }

            // refill other A buffer for next chunk during taps 2..4
            if (chunk < 3 && tap >= 2 && tap <= 4) {
                fill_A_rows(chunk + 1, (chunk + 1) & 1, tap - 2);
                CP_COMMIT();
            }

            // unpack current B fragments
            uint32_t b[4][4][2];
            #pragma unroll
            for (int u = 0; u < 4; ++u) {
                b[0][u][0] = __float_as_uint(bx[par][u * 2 + 0].x);
                b[0][u][1] = __float_as_uint(bx[par][u * 2 + 0].y);
                b[1][u][0] = __float_as_uint(bx[par][u * 2 + 0].z);
                b[1][u][1] = __float_as_uint(bx[par][u * 2 + 0].w);
                b[2][u][0] = __float_as_uint(bx[par][u * 2 + 1].x);
                b[2][u][1] = __float_as_uint(bx[par][u * 2 + 1].y);
                b[3][u][0] = __float_as_uint(bx[par][u * 2 + 1].z);
                b[3][u][1] = __float_as_uint(bx[par][u * 2 + 1].w);
            }

            const int kh = tap / 3, kw = tap - kh * 3;
            const float* At = As + ((kh - 1) * HC + (kw - 1)) * AROW;

            #pragma unroll
            for (int t = 0; t < 7; ++t) {
                const float* p0 = At + abase[t][0];
                const float* p1 = At + abase[t][1];
                uint32_t a[4][4];              // [j][4]
                #pragma unroll
                for (int j = 0; j < 4; ++j) {
                    const float2 lo = *(const float2*)(p0 + j * 8);
                    const float2 hi = *(const float2*)(p1 + j * 8);
                    a[j][0] = __float_as_uint(lo.x);
                    a[j][1] = __float_as_uint(hi.x);
                    a[j][2] = __float_as_uint(lo.y);
                    a[j][3] = __float_as_uint(hi.y);
                }
                #pragma unroll
                for (int j = 0; j < 4; ++j)
                    #pragma unroll
                    for (int u = 0; u < 4; ++u)
                        mma_tf32(acc[t][u], a[j], b[j][u][0], b[j][u][1]);
            }
        }
    }

    // ---------------- epilogue: bias + store ----------------
    const int pixbase = n * (CH * CW) + h0 * CW;
    float bv0[4], bv1[4];
    #pragma unroll
    for (int u = 0; u < 4; ++u) {
        const int c = bn * BN + warp_n * 32 + u * 8 + lc * 2;
        bv0[u] = bias[c];
        bv1[u] = bias[c + 1];
    }
    #pragma unroll
    for (int t = 0; t < 7; ++t) {
        const int m0 = warp_m * 112 + t * 16 + lr;
        #pragma unroll
        for (int u = 0; u < 4; ++u) {
            const int c = bn * BN + warp_n * 32 + u * 8 + lc * 2;
            float2 v0 = make_float2(acc[t][u][0] + bv0[u], acc[t][u][1] + bv1[u]);
            float2 v1 = make_float2(acc[t][u][2] + bv0[u], acc[t][u][3] + bv1[u]);
            *(float2*)(out + (size_t)(pixbase + m0) * CCOUT + c)     = v0;
            *(float2*)(out + (size_t)(pixbase + m0 + 8) * CCOUT + c) = v1;
        }
    }
}

// ---------------- host launch ----------------
extern "C" void kernel_launch(void* const* d_in, const int* in_sizes, int n_in,
                              void* d_out, int out_size)
{
    const float* x    = (const float*)d_in[0];
    const float* w    = (const float*)d_in[1];
    const float* bias = (const float*)d_in[2];
    float* out = (float*)d_out;

    float *gx = nullptr, *gwf = nullptr;
    cudaGetSymbolAddress((void**)&gx, g_x_t);
    cudaGetSymbolAddress((void**)&gwf, g_w_f);

    // merged pre-pass: x tf32+permute, w -> per-lane fragment pack
    k_prep<<<XGROUPS + WFRAG_TOTAL / 256, 256>>>(x, w, gx, gwf);

    cudaFuncSetAttribute(conv_mma, cudaFuncAttributeMaxDynamicSharedMemorySize,
                         SMEM_BYTES);
    // grid: 4 cout-blocks x (32 images * 14 row-blocks) = 1792 CTAs
    dim3 grid(CCOUT / BN, CB * (CH / 4));
    conv_mma<<<grid, NTHREADS, SMEM_BYTES>>>(gx, gwf, bias, out);
}

// round 14
// speedup vs baseline: 1.1697x; 1.1697x over previous
#include <cuda_runtime.h>
#include <cstdint>

// SAME-padded stride-1 3x3 conv, NHWC fp32, tf32 mma.sync implicit GEMM.
// Round 14: R12 (halo-A double buffer, pre-packed B via LDG.128, 4 syncs)
// + explicit A-fragment double buffer across the m-tile loop: tile t+1's
// LDS issue under tile t's MMAs -> hide shared-memory latency in-warp.
// CTA = 8 rows x 56 cols of one image (BM=448) x BN=64, 8 warps (112x32).

#define CB    32
#define CH    56
#define CW    56
#define CCIN  128
#define CCOUT 256
#define NPIX  (CB * CH * CW)      // 100352
#define KTOT  1152

#define BM 448                    // 8 rows x 56
#define BN 64
#define NTHREADS 256              // 8 warps, 4(M) x 2(N), warp 112x32

#define HR 10                     // halo rows  (8 + 2)
#define HC 58                     // halo cols  (56 + 2)
#define HPIX (HR * HC)            // 580
#define AROW 40                   // words per halo pixel (32 data + 8 pad)
#define A_STAGE_W (HPIX * AROW)   // 23200 words (92800 B)
#define SMEM_BYTES (2 * A_STAGE_W * 4)   // 185600

#define XGROUPS (NPIX * CCIN / 8 / 256)  // 6272 blocks for x-prep
#define WFRAG_TOTAL (KTOT * CCOUT)       // 294912 floats

// ---------------- scratch ----------------
__device__ __align__(1024) float g_x_t[NPIX * CCIN];     // tf32(rne), cin-permuted
// w_frag: [B0=8][tap=9][chunk=4][u=4][jh=2][lane=32][q=4] floats
__device__ __align__(1024) float g_w_f[WFRAG_TOTAL];

// ---------------- helpers ----------------
__device__ __forceinline__ uint32_t smem_u32(const void* p) {
    uint32_t a;
    asm("{ .reg .u64 t; cvta.to.shared.u64 t, %1; cvt.u32.u64 %0, t; }"
        : "=r"(a) : "l"(p));
    return a;
}

__device__ __forceinline__ void cp16(uint32_t dst, const void* src, uint32_t srcsz) {
    asm volatile("cp.async.cg.shared.global [%0], [%1], 16, %2;"
                 :: "r"(dst), "l"(src), "r"(srcsz) : "memory");
}
#define CP_COMMIT() asm volatile("cp.async.commit_group;" ::: "memory")
#define CP_WAIT0()  asm volatile("cp.async.wait_group 0;" ::: "memory")

__device__ __forceinline__ void mma_tf32(float c[4], const uint32_t a[4],
                                         uint32_t b0, uint32_t b1) {
    asm volatile(
        "mma.sync.aligned.m16n8k8.row.col.f32.tf32.tf32.f32 "
        "{%0,%1,%2,%3}, {%4,%5,%6,%7}, {%8,%9}, {%0,%1,%2,%3};"
        : "+f"(c[0]), "+f"(c[1]), "+f"(c[2]), "+f"(c[3])
        : "r"(a[0]), "r"(a[1]), "r"(a[2]), "r"(a[3]),
          "r"(b0), "r"(b1));
}

__device__ __forceinline__ float rna_tf32(float v) {
    uint32_t r;
    asm("cvt.rna.tf32.f32 %0, %1;" : "=r"(r) : "f"(v));
    return __uint_as_float(r);
}

// ---------------- merged pre-kernel (unchanged from R12) ----------------
__global__ void k_prep(const float* __restrict__ x, const float* __restrict__ w,
                       float* __restrict__ gx, float* __restrict__ gwf)
{
    const int bid = blockIdx.x;
    if (bid < XGROUPS) {
        const int g = bid * 256 + threadIdx.x;
        const float4* i4 = (const float4*)(x) + g * 2;
        float4 a = i4[0];   // c0..c3
        float4 b = i4[1];   // c4..c7
        float4 o0, o1;
        o0.x = rna_tf32(a.x); o0.y = rna_tf32(b.x);
        o0.z = rna_tf32(a.y); o0.w = rna_tf32(b.y);
        o1.x = rna_tf32(a.z); o1.y = rna_tf32(b.z);
        o1.z = rna_tf32(a.w); o1.w = rna_tf32(b.w);
        float4* o4 = (float4*)(gx) + g * 2;
        o4[0] = o0;
        o4[1] = o1;
    } else {
        const int f = (bid - XGROUPS) * 256 + threadIdx.x;  // 0..294911
        const int q     = f & 3;
        const int lane  = (f >> 2) & 31;
        const int jh    = (f >> 7) & 1;
        const int u     = (f >> 8) & 3;
        const int chunk = (f >> 10) & 3;
        const int rem   = f >> 12;          // B0*9 + tap
        const int B0    = rem / 9;
        const int tap   = rem - B0 * 9;
        const int lr = lane >> 2, lc = lane & 3;
        const int j = jh * 2 + (q >> 1);
        const int e = q & 1;
        const int cin  = (chunk * 4 + j) * 8 + lc + e * 4;
        const int cout = B0 * 32 + u * 8 + lr;
        gwf[f] = rna_tf32(w[(size_t)(tap * 128 + cin) * CCOUT + cout]);
    }
}

// ---------------- main kernel ----------------
__global__ __launch_bounds__(NTHREADS, 1)
void conv_mma(const float* __restrict__ xt, const float* __restrict__ wf,
              const float* __restrict__ bias, float* __restrict__ out)
{
    extern __shared__ float smem[];
    const uint32_t sbase = smem_u32(smem);

    const int tid  = threadIdx.x;
    const int wid  = tid >> 5;
    const int lane = tid & 31;
    const int lr   = lane >> 2;    // 0..7
    const int lc   = lane & 3;     // 0..3
    const int bn = blockIdx.x;     // 0..3   (cout block of 64)
    const int n  = blockIdx.y / 7;           // image
    const int h0 = (blockIdx.y % 7) * 8;     // first output row

    const int warp_m = wid >> 1;   // 0..3
    const int warp_n = wid & 1;    // 0..1

    // ---- fragment A base offsets (words, incl. lc*2 k-offset) ----
    int abase[7][2];
    #pragma unroll
    for (int t = 0; t < 7; ++t)
        #pragma unroll
        for (int h = 0; h < 2; ++h) {
            const int m = warp_m * 112 + t * 16 + lr + h * 8;   // 0..447
            const int r = m / 56, c = m % 56;
            abase[t][h] = ((r + 1) * HC + (c + 1)) * AROW + lc * 2;
        }

    const float* xbase = xt + (size_t)(n * (CH * CW)) * CCIN;
    const float4* wf4 = (const float4*)(wf)
                      + (size_t)(bn * 2 + warp_n) * (36 * 256) + lane;

    float acc[7][4][4];
    #pragma unroll
    for (int t = 0; t < 7; ++t)
        #pragma unroll
        for (int u = 0; u < 4; ++u)
            #pragma unroll
            for (int r = 0; r < 4; ++r)
                acc[t][u][r] = 0.0f;

    // ---- fill 2 halo rows (rq = 0..4) of A buffer `buf` for `chunk` ----
    auto fill_A_rows = [&](int chunk, int buf, int rq) {
        const uint32_t dst0 = sbase + (uint32_t)buf * (A_STAGE_W * 4);
        for (int idx = tid; idx < 2 * HC * 8; idx += NTHREADS) {
            const int pix = idx >> 3;            // 0..115
            const int seg = idx & 7;
            const int hr = (pix >= HC) ? 1 : 0;
            const int wc = pix - hr * HC;
            const int h = h0 - 1 + rq * 2 + hr, w2 = wc - 1;
            const bool ok = ((unsigned)h < CH) && ((unsigned)w2 < CW);
            const float* src = xbase
                + (ok ? ((size_t)(h * CW + w2) * CCIN + chunk * 32 + seg * 4) : 0);
            cp16(dst0 + (uint32_t)(rq * 2 * HC + pix) * (AROW * 4) + seg * 16,
                 src, ok ? 16u : 0u);
        }
    };

    // ---- A fragment loader: 8 LDS.64 for m-tile t at tap base At ----
    auto load_a = [&](uint32_t dst[4][4], const float* At, int t) {
        const float* p0 = At + abase[t][0];
        const float* p1 = At + abase[t][1];
        #pragma unroll
        for (int j = 0; j < 4; ++j) {
            const float2 lo = *(const float2*)(p0 + j * 8);
            const float2 hi = *(const float2*)(p1 + j * 8);
            dst[j][0] = __float_as_uint(lo.x);
            dst[j][1] = __float_as_uint(hi.x);
            dst[j][2] = __float_as_uint(lo.y);
            dst[j][3] = __float_as_uint(hi.y);
        }
    };

    // ---- prologue: A(chunk0) ----
    #pragma unroll
    for (int rq = 0; rq < 5; ++rq) fill_A_rows(0, 0, rq);
    CP_COMMIT();

    #pragma unroll 1
    for (int chunk = 0; chunk < 4; ++chunk) {
        CP_WAIT0();           // A(chunk) resident
        __syncthreads();

        const float* As = smem + (chunk & 1) * A_STAGE_W;

        #pragma unroll 1
        for (int tap = 0; tap < 9; ++tap) {
            // refill other A buffer for next chunk during taps 2..6
            if (chunk < 3 && tap >= 2 && tap <= 6) {
                fill_A_rows(chunk + 1, (chunk + 1) & 1, tap - 2);
                CP_COMMIT();
            }

            // ---- B fragments: 8 coalesced LDG.128 (L1-resident) ----
            const float4* wt4 = wf4 + (tap * 4 + chunk) * 256;
            float4 bx[8];
            #pragma unroll
            for (int ui = 0; ui < 8; ++ui)
                bx[ui] = wt4[ui * 32];

            uint32_t b[4][4][2];
            #pragma unroll
            for (int u = 0; u < 4; ++u) {
                b[0][u][0] = __float_as_uint(bx[u * 2 + 0].x);
                b[0][u][1] = __float_as_uint(bx[u * 2 + 0].y);
                b[1][u][0] = __float_as_uint(bx[u * 2 + 0].z);
                b[1][u][1] = __float_as_uint(bx[u * 2 + 0].w);
                b[2][u][0] = __float_as_uint(bx[u * 2 + 1].x);
                b[2][u][1] = __float_as_uint(bx[u * 2 + 1].y);
                b[3][u][0] = __float_as_uint(bx[u * 2 + 1].z);
                b[3][u][1] = __float_as_uint(bx[u * 2 + 1].w);
            }

            const int kh = tap / 3, kw = tap - kh * 3;
            const float* At = As + ((kh - 1) * HC + (kw - 1)) * AROW;

            // ---- m-tile loop, A fragments double-buffered ----
            uint32_t a[2][4][4];
            load_a(a[0], At, 0);
            #pragma unroll
            for (int t = 0; t < 7; ++t) {
                const int cur = t & 1;
                if (t < 6) load_a(a[cur ^ 1], At, t + 1);
                #pragma unroll
                for (int j = 0; j < 4; ++j)
                    #pragma unroll
                    for (int u = 0; u < 4; ++u)
                        mma_tf32(acc[t][u], a[cur][j], b[j][u][0], b[j][u][1]);
            }
        }
    }

    // ---------------- epilogue: bias + store ----------------
    const int pixbase = n * (CH * CW) + h0 * CW;
    float bv0[4], bv1[4];
    #pragma unroll
    for (int u = 0; u < 4; ++u) {
        const int c = bn * BN + warp_n * 32 + u * 8 + lc * 2;
        bv0[u] = bias[c];
        bv1[u] = bias[c + 1];
    }
    #pragma unroll
    for (int t = 0; t < 7; ++t) {
        const int m0 = warp_m * 112 + t * 16 + lr;
        #pragma unroll
        for (int u = 0; u < 4; ++u) {
            const int c = bn * BN + warp_n * 32 + u * 8 + lc * 2;
            float2 v0 = make_float2(acc[t][u][0] + bv0[u], acc[t][u][1] + bv1[u]);
            float2 v1 = make_float2(acc[t][u][2] + bv0[u], acc[t][u][3] + bv1[u]);
            *(float2*)(out + (size_t)(pixbase + m0) * CCOUT + c)     = v0;
            *(float2*)(out + (size_t)(pixbase + m0 + 8) * CCOUT + c) = v1;
        }
    }
}

// ---------------- host launch ----------------
extern "C" void kernel_launch(void* const* d_in, const int* in_sizes, int n_in,
                              void* d_out, int out_size)
{
    const float* x    = (const float*)d_in[0];
    const float* w    = (const float*)d_in[1];
    const float* bias = (const float*)d_in[2];
    float* out = (float*)d_out;

    float *gx = nullptr, *gwf = nullptr;
    cudaGetSymbolAddress((void**)&gx, g_x_t);
    cudaGetSymbolAddress((void**)&gwf, g_w_f);

    // merged pre-pass: x tf32+permute, w -> per-lane fragment pack
    k_prep<<<XGROUPS + WFRAG_TOTAL / 256, 256>>>(x, w, gx, gwf);

    cudaFuncSetAttribute(conv_mma, cudaFuncAttributeMaxDynamicSharedMemorySize,
                         SMEM_BYTES);
    // grid: 4 cout-blocks x (32 images * 7 row-blocks) = 896 CTAs
    dim3 grid(CCOUT / BN, CB * (CH / 8));
    conv_mma<<<grid, NTHREADS, SMEM_BYTES>>>(gx, gwf, bias, out);
}